// round 8
// baseline (speedup 1.0000x reference)
#include <cuda_runtime.h>

// Signature transform, depth 4, d=8, B=32, L=1024.
// Phase 1: per-(batch,chunk) sequential Chen fold over 64 increments,
//          whole truncated-tensor state held in registers (no barriers in loop).
// Phase 2: log2 tree of pairwise Chen combines; final round writes d_out.

namespace {
constexpr int kB = 32;
constexpr int kL = 1024;
constexpr int kD = 8;
constexpr int kNChunk = 16;
constexpr int kChunk = kL / kNChunk;          // 64 increments per chunk (incl. 1 zero pad)
constexpr int kSig = 8 + 64 + 512 + 4096;     // 4680 floats per signature
constexpr int kO1 = 0, kO2 = 8, kO3 = 72, kO4 = 584;
}

__device__ float g_sig[kB * kNChunk * kSig];  // 9.6 MB scratch

// ---------------------------------------------------------------------------
// Phase 1: chunk signatures.
// 128 threads: thread t owns (a = t>>4, b = (t>>1)&7), c in {4*(t&1) .. +3}, all e.
// State: S1[a], S2[a,b] replicated per owning thread; S3[a,b,c] (4 regs),
// S4[a,b,c,e] (32 regs) thread-private. Update is pure Horner.
// ---------------------------------------------------------------------------
__global__ __launch_bounds__(128) void sig_phase1(const float* __restrict__ path) {
  const int b  = blockIdx.y;
  const int ch = blockIdx.x;
  const int t  = threadIdx.x;

  __shared__ __align__(16) float sInc[kChunk * kD];

  // Cooperative load of this chunk's increments (zero-pad at global step L-1).
  for (int i = t; i < kChunk * kD; i += 128) {
    const int st = i >> 3, j = i & 7;
    const int g = ch * kChunk + st;
    float v = 0.f;
    if (g < kL - 1) {
      const float* pr = path + ((size_t)b * kL + g) * kD + j;
      v = pr[kD] - pr[0];
    }
    sInc[i] = v;
  }
  __syncthreads();

  const int a    = t >> 4;
  const int bb   = (t >> 1) & 7;
  const int half = t & 1;

  float s1 = 0.f, s2 = 0.f;
  float s3[4] = {0.f, 0.f, 0.f, 0.f};
  float r4[4][8];
#pragma unroll
  for (int j = 0; j < 4; ++j)
#pragma unroll
    for (int e = 0; e < 8; ++e) r4[j][e] = 0.f;

  for (int st = 0; st < kChunk; ++st) {
    const float* p = sInc + st * kD;
    const float4 plo = *reinterpret_cast<const float4*>(p);
    const float4 phi = *reinterpret_cast<const float4*>(p + 4);
    const float pe[8] = {plo.x, plo.y, plo.z, plo.w, phi.x, phi.y, phi.z, phi.w};
    const float pa = p[a];    // broadcast LDS (warp-uniform-ish)
    const float pb = p[bb];

    // All RHS use OLD state; commit at the end of the step.
    const float m  = fmaf(1.f / 24.f, pa, (1.f / 6.f) * s1);  // S1/6 + pa/24
    const float gg = fmaf(pb, m, 0.5f * s2);                  // S2/2 + pb*m
    const float m2 = fmaf(1.f / 6.f, pa, 0.5f * s1);          // S1/2 + pa/6
    const float g2 = fmaf(pb, m2, s2);                        // S2 + pb*m2
    const float n2 = fmaf(pb, fmaf(0.5f, pa, s1), s2);        // S2 + pb*(S1 + pa/2)

#pragma unroll
    for (int j = 0; j < 4; ++j) {
      const float pc = half ? pe[4 + j] : pe[j];
      const float t4 = fmaf(pc, gg, s3[j]);  // S3 + pc*(S2/2 + pb*(S1/6 + pa/24))
      const float n3 = fmaf(pc, g2, s3[j]);  // S3 + pc*(S2 + pb*(S1/2 + pa/6))
#pragma unroll
      for (int e = 0; e < 8; ++e) r4[j][e] = fmaf(t4, pe[e], r4[j][e]);
      s3[j] = n3;
    }
    s2 = n2;
    s1 += pa;
  }

  // Write chunk signature to scratch.
  float* out = g_sig + ((size_t)b * kNChunk + ch) * kSig;
#pragma unroll
  for (int j = 0; j < 4; ++j) {
    *reinterpret_cast<float4*>(out + kO4 + t * 32 + j * 8) =
        make_float4(r4[j][0], r4[j][1], r4[j][2], r4[j][3]);
    *reinterpret_cast<float4*>(out + kO4 + t * 32 + j * 8 + 4) =
        make_float4(r4[j][4], r4[j][5], r4[j][6], r4[j][7]);
  }
  // S3 flat index (a*8+b)*8 + half*4 + j == t*4 + j
  *reinterpret_cast<float4*>(out + kO3 + t * 4) = make_float4(s3[0], s3[1], s3[2], s3[3]);
  if (!half) out[kO2 + (t >> 1)] = s2;          // one writer per S2 element
  if ((t & 15) == 0) out[kO1 + a] = s1;         // one writer per S1 element
}

// ---------------------------------------------------------------------------
// Phase 2: pairwise Chen combine. A <- A (x) B (truncated, depth 4).
// C4 = A4 + B4 + A3(x)B1 + A2(x)B2 + A1(x)B3
// C3 = A3 + B3 + A2(x)B1 + A1(x)B2 ; C2 = A2 + B2 + A1(x)B1 ; C1 = A1 + B1
// 512 threads: thread t owns (a,b,c) = t and its 8 e-values of level 4.
// Final round (outp != nullptr) writes the output layout directly.
// ---------------------------------------------------------------------------
__global__ __launch_bounds__(512) void sig_combine(int stride, float* __restrict__ outp) {
  const int b  = blockIdx.y;
  const int iA = blockIdx.x * (stride << 1);
  float* A        = g_sig + ((size_t)b * kNChunk + iA) * kSig;
  const float* Bv = g_sig + ((size_t)b * kNChunk + iA + stride) * kSig;

  __shared__ __align__(16) float a3s[512], b3s[512];
  __shared__ __align__(16) float a2s[64], b2s[64];
  __shared__ __align__(16) float a1s[8], b1s[8];

  const int t = threadIdx.x;
  a3s[t] = A[kO3 + t];
  b3s[t] = Bv[kO3 + t];
  if (t < 64) { a2s[t] = A[kO2 + t]; b2s[t] = Bv[kO2 + t]; }
  if (t < 8)  { a1s[t] = A[kO1 + t]; b1s[t] = Bv[kO1 + t]; }

  const float4 A4lo = *reinterpret_cast<const float4*>(A + kO4 + t * 8);
  const float4 A4hi = *reinterpret_cast<const float4*>(A + kO4 + t * 8 + 4);
  const float4 B4lo = *reinterpret_cast<const float4*>(Bv + kO4 + t * 8);
  const float4 B4hi = *reinterpret_cast<const float4*>(Bv + kO4 + t * 8 + 4);
  __syncthreads();

  const int aa = t >> 6;
  const int bbq = (t >> 3) & 7;
  const int cc = t & 7;

  const float va3 = a3s[t];
  const float va2 = a2s[t >> 3];
  const float va1 = a1s[aa];

  const float A4[8] = {A4lo.x, A4lo.y, A4lo.z, A4lo.w, A4hi.x, A4hi.y, A4hi.z, A4hi.w};
  const float B4[8] = {B4lo.x, B4lo.y, B4lo.z, B4lo.w, B4hi.x, B4hi.y, B4hi.z, B4hi.w};

  const float4 b1v0 = *reinterpret_cast<const float4*>(b1s);
  const float4 b1v1 = *reinterpret_cast<const float4*>(b1s + 4);
  const float b1r[8] = {b1v0.x, b1v0.y, b1v0.z, b1v0.w, b1v1.x, b1v1.y, b1v1.z, b1v1.w};
  const float4 b2v0 = *reinterpret_cast<const float4*>(b2s + cc * 8);
  const float4 b2v1 = *reinterpret_cast<const float4*>(b2s + cc * 8 + 4);
  const float b2r[8] = {b2v0.x, b2v0.y, b2v0.z, b2v0.w, b2v1.x, b2v1.y, b2v1.z, b2v1.w};
  const float4 b3v0 = *reinterpret_cast<const float4*>(b3s + (t & 63) * 8);
  const float4 b3v1 = *reinterpret_cast<const float4*>(b3s + (t & 63) * 8 + 4);
  const float b3r[8] = {b3v0.x, b3v0.y, b3v0.z, b3v0.w, b3v1.x, b3v1.y, b3v1.z, b3v1.w};

  float c4[8];
#pragma unroll
  for (int e = 0; e < 8; ++e)
    c4[e] = A4[e] + B4[e] + va3 * b1r[e] + va2 * b2r[e] + va1 * b3r[e];

  const float c3 = va3 + b3s[t] + va2 * b1s[cc] + va1 * b2s[bbq * 8 + cc];
  float c2 = 0.f, c1 = 0.f;
  if (t < 64) c2 = a2s[t] + b2s[t] + a1s[t >> 3] * b1s[t & 7];
  if (t < 8)  c1 = a1s[t] + b1s[t];

  if (outp) {
    // Output layout: [L1: B*8][L2: B*64][L3: B*512][L4: B*4096]
    float* o4 = outp + kB * (8 + 64 + 512) + (size_t)b * 4096 + t * 8;
    *reinterpret_cast<float4*>(o4)     = make_float4(c4[0], c4[1], c4[2], c4[3]);
    *reinterpret_cast<float4*>(o4 + 4) = make_float4(c4[4], c4[5], c4[6], c4[7]);
    outp[kB * (8 + 64) + b * 512 + t] = c3;
    if (t < 64) outp[kB * 8 + b * 64 + t] = c2;
    if (t < 8)  outp[b * 8 + t] = c1;
  } else {
    *reinterpret_cast<float4*>(A + kO4 + t * 8)     = make_float4(c4[0], c4[1], c4[2], c4[3]);
    *reinterpret_cast<float4*>(A + kO4 + t * 8 + 4) = make_float4(c4[4], c4[5], c4[6], c4[7]);
    A[kO3 + t] = c3;
    if (t < 64) A[kO2 + t] = c2;
    if (t < 8)  A[kO1 + t] = c1;
  }
}

extern "C" void kernel_launch(void* const* d_in, const int* in_sizes, int n_in,
                              void* d_out, int out_size) {
  (void)in_sizes; (void)n_in; (void)out_size;
  const float* path = (const float*)d_in[0];
  float* out = (float*)d_out;

  sig_phase1<<<dim3(kNChunk, kB), 128>>>(path);
  sig_combine<<<dim3(8, kB), 512>>>(1, nullptr);   // 16 -> 8
  sig_combine<<<dim3(4, kB), 512>>>(2, nullptr);   //  8 -> 4
  sig_combine<<<dim3(2, kB), 512>>>(4, nullptr);   //  4 -> 2
  sig_combine<<<dim3(1, kB), 512>>>(8, out);       //  2 -> 1, write output
}